// round 5
// baseline (speedup 1.0000x reference)
#include <cuda_runtime.h>
#include <math.h>
#include <stdint.h>

#define BATCH 8
#define NTOK  1024
#define CDIM  768
#define NHEAD 12
#define HDIM  64
#define NTOTC 2304
#define MROWS 8192

// -------- scratch: tf32 fragment-major Q/K/V (device globals) --------
// g_q: A-frags [bh][rb(64)][ks(8)][lane(32)][4]   (16-row blocks)
// g_k: B-frags [bh][nfr(128)][ks(8)][lane(32)][2] (8-kv blocks, k=dims)
// g_v: B-frags [bh][kfr(128)][nt(8)][lane(32)][2] (8-kv k-blocks, n=dims)
__device__ float g_q[BATCH * NHEAD * NTOK * HDIM];
__device__ float g_k[BATCH * NHEAD * NTOK * HDIM];
__device__ float g_v[BATCH * NHEAD * NTOK * HDIM];

// ============================================================================
// helpers
// ============================================================================
__device__ __forceinline__ uint32_t smem_u32(const void* p) {
    uint32_t a;
    asm("{ .reg .u64 t; cvta.to.shared.u64 t, %1; cvt.u32.u64 %0, t; }"
        : "=r"(a) : "l"(p));
    return a;
}
__device__ __forceinline__ uint32_t f2tf32(float x) {
    uint32_t r;
    asm("cvt.rna.tf32.f32 %0, %1;" : "=r"(r) : "f"(x));
    return r;
}
__device__ __forceinline__ void sts32(uint32_t a, uint32_t v) {
    asm volatile("st.shared.b32 [%0], %1;" :: "r"(a), "r"(v) : "memory");
}
__device__ __forceinline__ void lds128(uint32_t* r, uint32_t a) {
    asm volatile("ld.shared.v4.b32 {%0,%1,%2,%3}, [%4];"
                 : "=r"(r[0]), "=r"(r[1]), "=r"(r[2]), "=r"(r[3]) : "r"(a));
}
__device__ __forceinline__ void mma8(float4& d,
                                     uint32_t a0, uint32_t a1, uint32_t a2, uint32_t a3,
                                     uint32_t b0, uint32_t b1) {
    asm volatile(
        "mma.sync.aligned.m16n8k8.row.col.f32.tf32.tf32.f32 "
        "{%0,%1,%2,%3}, {%4,%5,%6,%7}, {%8,%9}, {%0,%1,%2,%3};"
        : "+f"(d.x), "+f"(d.y), "+f"(d.z), "+f"(d.w)
        : "r"(a0), "r"(a1), "r"(a2), "r"(a3), "r"(b0), "r"(b1));
}

// ============================================================================
// Kernel 1: fused QKV projection, tf32 mma.sync, double-buffered smem,
// epilogue writes fragment-major tf32 Q/K/V.
// ============================================================================
#define ASTR 36
#define CHWORDS (128 * ASTR)          // 4608 words per buffer
#define QKV_SMEM_BYTES (4 * CHWORDS * 4)  // 73728

__global__ __launch_bounds__(256, 2)
void qkv_tc(const float* __restrict__ x,
            const float* __restrict__ Wq,  const float* __restrict__ bq,
            const float* __restrict__ Wkv, const float* __restrict__ bkv)
{
    extern __shared__ uint32_t qsm[];
    // As buf b: qsm[b*CHWORDS ...], Bs buf b: qsm[2*CHWORDS + b*CHWORDS ...]

    const int tid  = threadIdx.x;
    const int wid  = tid >> 5;
    const int lane = tid & 31;
    const int g    = lane >> 2;
    const int tig  = lane & 3;
    const int mBase = blockIdx.y * 128;
    const int nBase = blockIdx.x * 128;
    const int wm = (wid >> 1) * 32;
    const int wn = (wid & 1) * 64;

    const int lrow  = tid >> 1;
    const int lcol0 = (tid & 1) * 16;
    const float* Ag = x + (size_t)(mBase + lrow) * CDIM + lcol0;
    const int nrow = nBase + lrow;
    const float* Bg = (nrow < CDIM) ? (Wq + (size_t)nrow * CDIM + lcol0)
                                    : (Wkv + (size_t)(nrow - CDIM) * CDIM + lcol0);

    float4 ar[4], br[4];
#pragma unroll
    for (int i = 0; i < 4; i++) {
        ar[i] = *(const float4*)(Ag + 4 * i);
        br[i] = *(const float4*)(Bg + 4 * i);
    }

    float4 dacc[2][8];
#pragma unroll
    for (int mt = 0; mt < 2; mt++)
#pragma unroll
        for (int nt = 0; nt < 8; nt++) dacc[mt][nt] = make_float4(0.f, 0.f, 0.f, 0.f);

    for (int ch = 0; ch < 24; ch++) {
        const int bf = ch & 1;
        uint32_t* As = qsm + bf * CHWORDS;
        uint32_t* Bs = qsm + 2 * CHWORDS + bf * CHWORDS;

        // store current chunk (safe: prior readers of this buffer finished
        // before the previous iteration's barrier)
#pragma unroll
        for (int i = 0; i < 4; i++) {
            uint32_t* pa = &As[lrow * ASTR + lcol0 + 4 * i];
            pa[0] = f2tf32(ar[i].x); pa[1] = f2tf32(ar[i].y);
            pa[2] = f2tf32(ar[i].z); pa[3] = f2tf32(ar[i].w);
            uint32_t* pb = &Bs[lrow * ASTR + lcol0 + 4 * i];
            pb[0] = f2tf32(br[i].x); pb[1] = f2tf32(br[i].y);
            pb[2] = f2tf32(br[i].z); pb[3] = f2tf32(br[i].w);
        }
        __syncthreads();

        if (ch < 23) {
#pragma unroll
            for (int i = 0; i < 4; i++) {
                ar[i] = *(const float4*)(Ag + (ch + 1) * 32 + 4 * i);
                br[i] = *(const float4*)(Bg + (ch + 1) * 32 + 4 * i);
            }
        }

#pragma unroll
        for (int ks = 0; ks < 4; ks++) {
            const int k0 = ks * 8;
            uint32_t a[2][4];
#pragma unroll
            for (int mt = 0; mt < 2; mt++) {
                const int r0 = wm + mt * 16 + g;
                a[mt][0] = As[r0 * ASTR + k0 + tig];
                a[mt][1] = As[(r0 + 8) * ASTR + k0 + tig];
                a[mt][2] = As[r0 * ASTR + k0 + tig + 4];
                a[mt][3] = As[(r0 + 8) * ASTR + k0 + tig + 4];
            }
#pragma unroll
            for (int nt = 0; nt < 8; nt++) {
                const int nr = wn + nt * 8 + g;
                uint32_t b0 = Bs[nr * ASTR + k0 + tig];
                uint32_t b1 = Bs[nr * ASTR + k0 + tig + 4];
                mma8(dacc[0][nt], a[0][0], a[0][1], a[0][2], a[0][3], b0, b1);
                mma8(dacc[1][nt], a[1][0], a[1][1], a[1][2], a[1][3], b0, b1);
            }
        }
    }

    // ---- epilogue: bias, scale, write fragment-major tf32 ----
    const int cb = nBase + wn;          // 64-aligned: one dest, one head
    const int hh = (cb % 768) >> 6;
    const int bidx = mBase >> 10;       // tile never crosses a batch boundary
    const int bh = bidx * NHEAD + hh;
    const float* brow;
    if (cb < 768) brow = bq + cb; else brow = bkv + (cb - 768);

#pragma unroll
    for (int mt = 0; mt < 2; mt++) {
#pragma unroll
        for (int rr = 0; rr < 2; rr++) {
            const int row = mBase + wm + mt * 16 + g + rr * 8;
            const int tok = row & 1023;
#pragma unroll
            for (int nt = 0; nt < 8; nt++) {
#pragma unroll
                for (int j = 0; j < 2; j++) {
                    const int dd = nt * 8 + 2 * tig + j;
                    float v;
                    if (rr == 0) v = (j == 0) ? dacc[mt][nt].x : dacc[mt][nt].y;
                    else         v = (j == 0) ? dacc[mt][nt].z : dacc[mt][nt].w;
                    v += __ldg(brow + dd);
                    if (cb < 768) {
                        // Q: A-frag layout, scaled
                        const uint32_t tv = f2tf32(v * 0.125f);
                        const int rb = tok >> 4;
                        const int lq = (tok & 7) * 4 + (dd & 3);
                        const int rq = ((tok >> 3) & 1) + 2 * ((dd >> 2) & 1);
                        g_q[(size_t)(((bh * 64 + rb) * 8 + nt) * 128) + lq * 4 + rq]
                            = __uint_as_float(tv);
                    } else if (cb < 1536) {
                        // K: B-frag layout (n = token, k = dim)
                        const uint32_t tv = f2tf32(v);
                        const int lk = (tok & 7) * 4 + (dd & 3);
                        const int rk = (dd >> 2) & 1;
                        g_k[(size_t)(((bh * 128 + (tok >> 3)) * 8 + nt) * 64) + lk * 2 + rk]
                            = __uint_as_float(tv);
                    } else {
                        // V: B-frag layout (n = dim, k = token)
                        const uint32_t tv = f2tf32(v);
                        const int lv = (dd & 7) * 4 + (tok & 3);
                        const int rv = (tok >> 2) & 1;
                        g_v[(size_t)(((bh * 128 + (tok >> 3)) * 8 + nt) * 64) + lv * 2 + rv]
                            = __uint_as_float(tv);
                    }
                }
            }
        }
    }
}

// ============================================================================
// Kernel 2: flash attention, tf32 mma.sync, barrier-free.
// All MMA operands loaded as fragments via coalesced LDG (L1-hot).
// P round-trip stays in per-warp swizzled smem (syncwarp only).
// ============================================================================
__global__ __launch_bounds__(256, 2)
void flash_tc(const float* __restrict__ rel_bias, float* __restrict__ out)
{
    __shared__ uint32_t Psm[8 * 1024];   // 4KB per warp

    const int tid  = threadIdx.x;
    const int wid  = tid >> 5;
    const int lane = tid & 31;
    const int g    = lane >> 2;
    const int t    = lane & 3;
    const int qt   = blockIdx.x;
    const int bh   = blockIdx.y;
    const int b    = bh / NHEAD;
    const int h    = bh % NHEAD;

    // ---- Q A-fragments, register resident: 8 LDG.128 ----
    const uint32_t* qfb = (const uint32_t*)g_q
        + (size_t)((bh * 64 + qt * 8 + wid) * 8) * 128 + lane * 4;
    uint32_t qf[8][4];
#pragma unroll
    for (int ks = 0; ks < 8; ks++) {
        uint4 q4 = *(const uint4*)(qfb + ks * 128);
        qf[ks][0] = q4.x; qf[ks][1] = q4.y; qf[ks][2] = q4.z; qf[ks][3] = q4.w;
    }

    const uint32_t* kfb = (const uint32_t*)g_k + (size_t)bh * 65536 + lane * 2;
    const uint32_t* vfb = (const uint32_t*)g_v + (size_t)bh * 65536 + lane * 2;

    // ---- P smem addressing (same swizzle as R4) ----
    const uint32_t Pw = smem_u32(Psm) + (uint32_t)wid * 4096;
    const uint32_t swz = (uint32_t)((g >> 1) & 3);
    const uint32_t pA  = Pw + (uint32_t)(g * 4 + (t ^ swz)) * 16;
    const uint32_t pxz = Pw + (uint32_t)(g * 4 + (((2 * t) & 3) ^ swz)) * 16
                       + (uint32_t)(t >> 1) * 8;
    const uint32_t pyw = Pw + (uint32_t)(g * 4 + (((2 * t + 1) & 3) ^ swz)) * 16
                       + (uint32_t)(t >> 1) * 8;

    const int qrow0 = qt * 128 + wid * 16 + g;
    const int qi0 = qrow0 >> 5,       qj0 = qrow0 & 31;
    const int qi1 = (qrow0 + 8) >> 5, qj1 = (qrow0 + 8) & 31;

    float4 o[8];
#pragma unroll
    for (int nt = 0; nt < 8; nt++) o[nt] = make_float4(0.f, 0.f, 0.f, 0.f);
    float m0 = -INFINITY, m1 = -INFINITY, l0 = 0.f, l1 = 0.f;

    for (int kt = 0; kt < 16; kt++) {
        const uint32_t* kb = kfb + kt * 4096;
        const uint32_t* vb = vfb + kt * 4096;

        // ---- S = Q K^T : A regs, B via LDG.64 (L1-hot) ----
        float4 s[8];
#pragma unroll
        for (int nt = 0; nt < 8; nt++) s[nt] = make_float4(0.f, 0.f, 0.f, 0.f);
#pragma unroll
        for (int ks = 0; ks < 8; ks++) {
#pragma unroll
            for (int nt = 0; nt < 8; nt++) {
                const uint2 bf = *(const uint2*)(kb + (nt * 8 + ks) * 64);
                mma8(s[nt], qf[ks][0], qf[ks][1], qf[ks][2], qf[ks][3], bf.x, bf.y);
            }
        }

        // ---- bias + row max ----
        float mx0 = -INFINITY, mx1 = -INFINITY;
#pragma unroll
        for (int nt = 0; nt < 8; nt++) {
            const int col0 = kt * 64 + nt * 8 + 2 * t;
            const int ki = col0 >> 5;
            const int kj = col0 & 31;
            s[nt].x += __ldg(&rel_bias[((qi0 - ki + 31) * 63 + (qj0 - kj + 31)) * NHEAD + h]);
            s[nt].y += __ldg(&rel_bias[((qi0 - ki + 31) * 63 + (qj0 - kj + 30)) * NHEAD + h]);
            s[nt].z += __ldg(&rel_bias[((qi1 - ki + 31) * 63 + (qj1 - kj + 31)) * NHEAD + h]);
            s[nt].w += __ldg(&rel_bias[((qi1 - ki + 31) * 63 + (qj1 - kj + 30)) * NHEAD + h]);
            mx0 = fmaxf(mx0, fmaxf(s[nt].x, s[nt].y));
            mx1 = fmaxf(mx1, fmaxf(s[nt].z, s[nt].w));
        }
        mx0 = fmaxf(mx0, __shfl_xor_sync(0xffffffffu, mx0, 1));
        mx0 = fmaxf(mx0, __shfl_xor_sync(0xffffffffu, mx0, 2));
        mx1 = fmaxf(mx1, __shfl_xor_sync(0xffffffffu, mx1, 1));
        mx1 = fmaxf(mx1, __shfl_xor_sync(0xffffffffu, mx1, 2));

        const float mn0 = fmaxf(m0, mx0);
        const float mn1 = fmaxf(m1, mx1);
        const float al0 = __expf(m0 - mn0);
        const float al1 = __expf(m1 - mn1);
        float rs0 = 0.f, rs1 = 0.f;
#pragma unroll
        for (int nt = 0; nt < 8; nt++) {
            s[nt].x = __expf(s[nt].x - mn0);
            s[nt].y = __expf(s[nt].y - mn0);
            s[nt].z = __expf(s[nt].z - mn1);
            s[nt].w = __expf(s[nt].w - mn1);
            rs0 += s[nt].x + s[nt].y;
            rs1 += s[nt].z + s[nt].w;
            o[nt].x *= al0; o[nt].y *= al0;
            o[nt].z *= al1; o[nt].w *= al1;
        }
        rs0 += __shfl_xor_sync(0xffffffffu, rs0, 1);
        rs0 += __shfl_xor_sync(0xffffffffu, rs0, 2);
        rs1 += __shfl_xor_sync(0xffffffffu, rs1, 1);
        rs1 += __shfl_xor_sync(0xffffffffu, rs1, 2);
        l0 = l0 * al0 + rs0; m0 = mn0;
        l1 = l1 * al1 + rs1; m1 = mn1;

        // ---- P -> per-warp fragment smem (swizzled) ----
#pragma unroll
        for (int nt = 0; nt < 8; nt++) {
            sts32(pxz + nt * 512,     f2tf32(s[nt].x));
            sts32(pxz + nt * 512 + 4, f2tf32(s[nt].z));
            sts32(pyw + nt * 512,     f2tf32(s[nt].y));
            sts32(pyw + nt * 512 + 4, f2tf32(s[nt].w));
        }
        __syncwarp();

        // ---- O += P V : A via LDS.128, B via LDG.64 ----
#pragma unroll
        for (int ks = 0; ks < 8; ks++) {
            uint32_t pa[4];
            lds128(pa, pA + ks * 512);
#pragma unroll
            for (int nt = 0; nt < 8; nt++) {
                const uint2 bf = *(const uint2*)(vb + (ks * 8 + nt) * 64);
                mma8(o[nt], pa[0], pa[1], pa[2], pa[3], bf.x, bf.y);
            }
        }
        __syncwarp();   // PV reads done before next tile's P stores
    }

    // ---- epilogue ----
    const float inv0 = 1.f / l0;
    const float inv1 = 1.f / l1;
    float* out0 = out + (size_t)(b * NTOK + qrow0) * CDIM + h * HDIM;
    float* out1 = out + (size_t)(b * NTOK + qrow0 + 8) * CDIM + h * HDIM;
#pragma unroll
    for (int nt = 0; nt < 8; nt++) {
        const int dd = nt * 8 + 2 * t;
        *(float2*)(out0 + dd) = make_float2(o[nt].x * inv0, o[nt].y * inv0);
        *(float2*)(out1 + dd) = make_float2(o[nt].z * inv1, o[nt].w * inv1);
    }
}

// ============================================================================
extern "C" void kernel_launch(void* const* d_in, const int* in_sizes, int n_in,
                              void* d_out, int out_size)
{
    const float* x        = (const float*)d_in[0];
    const float* Wq       = (const float*)d_in[1];
    const float* bq       = (const float*)d_in[2];
    const float* Wkv      = (const float*)d_in[3];
    const float* bkv      = (const float*)d_in[4];
    const float* rel_bias = (const float*)d_in[5];
    float* out = (float*)d_out;

    cudaFuncSetAttribute(qkv_tc, cudaFuncAttributeMaxDynamicSharedMemorySize,
                         QKV_SMEM_BYTES);
    qkv_tc<<<dim3(NTOTC / 128, MROWS / 128), 256, QKV_SMEM_BYTES>>>(x, Wq, bq, Wkv, bkv);

    flash_tc<<<dim3(8, BATCH * NHEAD), 256>>>(rel_bias, out);
}

// round 6
// speedup vs baseline: 2.0762x; 2.0762x over previous
#include <cuda_runtime.h>
#include <cuda_fp16.h>
#include <math.h>
#include <stdint.h>

#define BATCH 8
#define NTOK  1024
#define CDIM  768
#define NHEAD 12
#define HDIM  64
#define NTOTC 2304
#define MROWS 8192

// -------- scratch: fp16 Q/K row-major, V transposed (device globals) --------
__device__ __align__(16) __half g_q [BATCH * NHEAD * NTOK * HDIM];
__device__ __align__(16) __half g_k [BATCH * NHEAD * NTOK * HDIM];
__device__ __align__(16) __half g_vT[BATCH * NHEAD * HDIM * NTOK];  // [bh][dim][tok]

// ============================================================================
// helpers
// ============================================================================
__device__ __forceinline__ uint32_t smem_u32(const void* p) {
    uint32_t a;
    asm("{ .reg .u64 t; cvta.to.shared.u64 t, %1; cvt.u32.u64 %0, t; }"
        : "=r"(a) : "l"(p));
    return a;
}
__device__ __forceinline__ uint32_t h2pack(float a, float b) {
    __half2 h = __floats2half2_rn(a, b);
    return *reinterpret_cast<uint32_t*>(&h);
}
// D += A(16x16) * B(16x8), fp16 inputs, f32 accumulate.
__device__ __forceinline__ void mma16(float4& d,
                                      uint32_t a0, uint32_t a1, uint32_t a2, uint32_t a3,
                                      uint32_t b0, uint32_t b1) {
    asm volatile(
        "mma.sync.aligned.m16n8k16.row.col.f32.f16.f16.f32 "
        "{%0,%1,%2,%3}, {%4,%5,%6,%7}, {%8,%9}, {%0,%1,%2,%3};"
        : "+f"(d.x), "+f"(d.y), "+f"(d.z), "+f"(d.w)
        : "r"(a0), "r"(a1), "r"(a2), "r"(a3), "r"(b0), "r"(b1));
}
__device__ __forceinline__ void cpasync16(uint32_t saddr, const void* gptr) {
    asm volatile("cp.async.cg.shared.global [%0], [%1], 16;"
                 :: "r"(saddr), "l"(gptr) : "memory");
}
#define CP_COMMIT() asm volatile("cp.async.commit_group;" ::: "memory")
#define CP_WAIT0()  asm volatile("cp.async.wait_group 0;" ::: "memory")
#define CP_WAIT1()  asm volatile("cp.async.wait_group 1;" ::: "memory")

// ============================================================================
// Kernel 1: fused QKV projection, fp16 m16n8k16.
// CTA 128x128, 8 warps (4M x 2N), K chunks of 32 (2 k16-steps).
// Epilogue: Q/K row-major fp16 (+bias, Q*0.125); V transposed via smem.
// ============================================================================
#define AW 20   // smem row stride in u32 words (16 data + 4 pad)

__global__ __launch_bounds__(256, 2)
void qkv_tc(const float* __restrict__ x,
            const float* __restrict__ Wq,  const float* __restrict__ bq,
            const float* __restrict__ Wkv, const float* __restrict__ bkv)
{
    __shared__ __align__(16) uint32_t qsm[2 * 128 * AW];   // 20480 B
    uint32_t* As = qsm;
    uint32_t* Bs = qsm + 128 * AW;

    const int tid  = threadIdx.x;
    const int wid  = tid >> 5;
    const int lane = tid & 31;
    const int g    = lane >> 2;
    const int tig  = lane & 3;
    const int mBase = blockIdx.y * 128;
    const int nBase = blockIdx.x * 128;
    const int wm = (wid >> 1) * 32;
    const int wn = (wid & 1) * 64;

    const int lrow  = tid >> 1;
    const int lcol0 = (tid & 1) * 16;
    const float* Ag = x + (size_t)(mBase + lrow) * CDIM + lcol0;
    const int nrow = nBase + lrow;
    const float* Bg = (nrow < CDIM) ? (Wq + (size_t)nrow * CDIM + lcol0)
                                    : (Wkv + (size_t)(nrow - CDIM) * CDIM + lcol0);
    const uint32_t abase = (uint32_t)lrow * AW + (uint32_t)(tid & 1) * 8;

    float4 ar[4], br[4];
#pragma unroll
    for (int i = 0; i < 4; i++) {
        ar[i] = *(const float4*)(Ag + 4 * i);
        br[i] = *(const float4*)(Bg + 4 * i);
    }

    float4 dacc[2][8];
#pragma unroll
    for (int mt = 0; mt < 2; mt++)
#pragma unroll
        for (int nt = 0; nt < 8; nt++) dacc[mt][nt] = make_float4(0.f, 0.f, 0.f, 0.f);

    for (int ch = 0; ch < 24; ch++) {
        // convert + store current chunk
        uint32_t aw[8], bw[8];
#pragma unroll
        for (int i = 0; i < 4; i++) {
            aw[2*i]   = h2pack(ar[i].x, ar[i].y);
            aw[2*i+1] = h2pack(ar[i].z, ar[i].w);
            bw[2*i]   = h2pack(br[i].x, br[i].y);
            bw[2*i+1] = h2pack(br[i].z, br[i].w);
        }
        *(uint4*)&As[abase]     = make_uint4(aw[0], aw[1], aw[2], aw[3]);
        *(uint4*)&As[abase + 4] = make_uint4(aw[4], aw[5], aw[6], aw[7]);
        *(uint4*)&Bs[abase]     = make_uint4(bw[0], bw[1], bw[2], bw[3]);
        *(uint4*)&Bs[abase + 4] = make_uint4(bw[4], bw[5], bw[6], bw[7]);
        __syncthreads();

        if (ch < 23) {
#pragma unroll
            for (int i = 0; i < 4; i++) {
                ar[i] = *(const float4*)(Ag + (ch + 1) * 32 + 4 * i);
                br[i] = *(const float4*)(Bg + (ch + 1) * 32 + 4 * i);
            }
        }

#pragma unroll
        for (int ks = 0; ks < 2; ks++) {
            const int k0 = ks * 8;
            uint32_t a[2][4];
#pragma unroll
            for (int mt = 0; mt < 2; mt++) {
                const int r0 = wm + mt * 16 + g;
                a[mt][0] = As[r0 * AW + k0 + tig];
                a[mt][1] = As[(r0 + 8) * AW + k0 + tig];
                a[mt][2] = As[r0 * AW + k0 + tig + 4];
                a[mt][3] = As[(r0 + 8) * AW + k0 + tig + 4];
            }
#pragma unroll
            for (int nt = 0; nt < 8; nt++) {
                const int nr = wn + nt * 8 + g;
                uint32_t b0 = Bs[nr * AW + k0 + tig];
                uint32_t b1 = Bs[nr * AW + k0 + tig + 4];
                mma16(dacc[0][nt], a[0][0], a[0][1], a[0][2], a[0][3], b0, b1);
                mma16(dacc[1][nt], a[1][0], a[1][1], a[1][2], a[1][3], b0, b1);
            }
        }
        __syncthreads();
    }

    const int bidx = mBase >> 10;

    if (nBase < 1536) {
        // ---- Q or K: direct fp16 row-major stores ----
        const int cb = nBase + wn;
        const bool isQ = (cb < 768);
        const float mul = isQ ? 0.125f : 1.f;
        const float* brow = isQ ? (bq + cb) : (bkv + (cb - 768));
        __half* dst = isQ ? g_q : g_k;
        const int hh = (cb % 768) >> 6;
        const int bh = bidx * NHEAD + hh;
#pragma unroll
        for (int mt = 0; mt < 2; mt++) {
#pragma unroll
            for (int rr = 0; rr < 2; rr++) {
                const int row = mBase + wm + mt * 16 + g + rr * 8;
                const int tok = row & 1023;
                uint32_t* orow = (uint32_t*)(dst + (size_t)(bh * NTOK + tok) * HDIM);
#pragma unroll
                for (int nt = 0; nt < 8; nt++) {
                    const int dd = nt * 8 + 2 * tig;
                    float v0, v1;
                    if (rr == 0) { v0 = dacc[mt][nt].x; v1 = dacc[mt][nt].y; }
                    else         { v0 = dacc[mt][nt].z; v1 = dacc[mt][nt].w; }
                    v0 = (v0 + __ldg(brow + dd)) * mul;
                    v1 = (v1 + __ldg(brow + dd + 1)) * mul;
                    orow[dd >> 1] = h2pack(v0, v1);
                }
            }
        }
    } else {
        // ---- V: transpose via smem, write g_vT[bh][dim][tok] ----
        __half* Vt = (__half*)qsm;   // [64][136] halves = 17408 B (fits 20480)
#pragma unroll
        for (int p = 0; p < 2; p++) {
            if (wn == p * 64) {
                const float* brow = bkv + (nBase + wn - 768);
#pragma unroll
                for (int mt = 0; mt < 2; mt++) {
#pragma unroll
                    for (int rr = 0; rr < 2; rr++) {
                        const int tokl = wm + mt * 16 + g + rr * 8;   // 0..127
#pragma unroll
                        for (int nt = 0; nt < 8; nt++) {
                            const int dd = nt * 8 + 2 * tig;
                            float v0, v1;
                            if (rr == 0) { v0 = dacc[mt][nt].x; v1 = dacc[mt][nt].y; }
                            else         { v0 = dacc[mt][nt].z; v1 = dacc[mt][nt].w; }
                            Vt[dd * 136 + tokl]       = __float2half_rn(v0 + __ldg(brow + dd));
                            Vt[(dd + 1) * 136 + tokl] = __float2half_rn(v1 + __ldg(brow + dd + 1));
                        }
                    }
                }
            }
            __syncthreads();
            // write out 64 dims x 128 toks, coalesced in tok
            const int hp = (nBase + p * 64 - 1536) >> 6;
            const int bh_p = bidx * NHEAD + hp;
            const int d = tid >> 2;
            const int tok0 = (tid & 3) * 32;
            const uint32_t* vtw = (const uint32_t*)Vt;
            uint32_t* odst = (uint32_t*)(g_vT + (size_t)(bh_p * HDIM + d) * NTOK
                                         + (mBase & 1023) + tok0);
#pragma unroll
            for (int i = 0; i < 4; i++) {
                uint4 val = *(const uint4*)(vtw + d * 68 + (tok0 >> 1) + 4 * i);
                *(uint4*)(odst + 4 * i) = val;
            }
            __syncthreads();
        }
    }
}

// ============================================================================
// Kernel 2: flash attention, fp16 m16n8k16.
// Grid (8, 96), 256 threads (8 warps), warp = 16 q rows x 64 kv.
// K/V tiles: cp.async double-buffered, row-major fp16 smem (conflict-free
// fragment LDS.32). P relayout = pure f16x2 register pack. No P smem.
// ============================================================================
#define KW 36   // smem row stride in u32 words (32 data + 4 pad)

__global__ __launch_bounds__(256, 2)
void flash_tc(const float* __restrict__ rel_bias, float* __restrict__ out)
{
    __shared__ __align__(16) uint32_t fsm[4 * 64 * KW];   // 36864 B

    const int tid  = threadIdx.x;
    const int wid  = tid >> 5;
    const int lane = tid & 31;
    const int g    = lane >> 2;
    const int t    = lane & 3;
    const int qt   = blockIdx.x;
    const int bh   = blockIdx.y;
    const int b    = bh / NHEAD;
    const int h    = bh % NHEAD;

    const uint32_t sb = smem_u32(fsm);
    const __half* kbh = g_k  + (size_t)bh * (NTOK * HDIM);
    const __half* vbh = g_vT + (size_t)bh * (HDIM * NTOK);

    // ---- Q A-fragments, register resident (fp16 row-major gmem) ----
    const int qrow0 = qt * 128 + wid * 16 + g;
    const uint32_t* qw = (const uint32_t*)g_q + (size_t)(bh * NTOK + qrow0) * 32;
    uint32_t qf[4][4];
#pragma unroll
    for (int kc = 0; kc < 4; kc++) {
        qf[kc][0] = __ldg(qw + kc * 8 + t);
        qf[kc][1] = __ldg(qw + 256 + kc * 8 + t);        // row +8 => +8*32 words
        qf[kc][2] = __ldg(qw + kc * 8 + t + 4);
        qf[kc][3] = __ldg(qw + 256 + kc * 8 + t + 4);
    }

    const int qi0 = qrow0 >> 5,       qj0 = qrow0 & 31;
    const int qi1 = (qrow0 + 8) >> 5, qj1 = (qrow0 + 8) & 31;

    float4 o[8];
#pragma unroll
    for (int nt = 0; nt < 8; nt++) o[nt] = make_float4(0.f, 0.f, 0.f, 0.f);
    float m0 = -INFINITY, m1 = -INFINITY, l0 = 0.f, l1 = 0.f;

    // cp.async tile issue: 512 x 16B per matrix, 2 chunks each per thread
#define ISSUE_TILE(kt_, bsel_)                                                  \
    do {                                                                        \
        const uint32_t kd = sb + (uint32_t)(bsel_) * (64 * KW * 4);             \
        const uint32_t vd = kd + 2 * (64 * KW * 4);                             \
        _Pragma("unroll")                                                       \
        for (int c = tid; c < 512; c += 256) {                                  \
            const int row = c >> 3, ii = c & 7;                                 \
            cpasync16(kd + (uint32_t)(row * KW + ii * 4) * 4,                   \
                      kbh + ((kt_) * 64 + row) * 64 + ii * 8);                  \
            cpasync16(vd + (uint32_t)(row * KW + ii * 4) * 4,                   \
                      vbh + row * NTOK + (kt_) * 64 + ii * 8);                  \
        }                                                                       \
    } while (0)

    ISSUE_TILE(0, 0);
    CP_COMMIT();

    for (int kt = 0; kt < 16; kt++) {
        if (kt < 15) {
            ISSUE_TILE(kt + 1, (kt + 1) & 1);
            CP_COMMIT();
            CP_WAIT1();
        } else {
            CP_WAIT0();
        }
        __syncthreads();

        const uint32_t* Kb = fsm + (kt & 1) * (64 * KW);
        const uint32_t* Vb = Kb + 2 * (64 * KW);

        // ---- S = Q K^T ----
        float4 s[8];
#pragma unroll
        for (int nt = 0; nt < 8; nt++) s[nt] = make_float4(0.f, 0.f, 0.f, 0.f);
#pragma unroll
        for (int kc = 0; kc < 4; kc++) {
#pragma unroll
            for (int nt = 0; nt < 8; nt++) {
                const uint32_t* bp = Kb + (nt * 8 + g) * KW + kc * 8 + t;
                mma16(s[nt], qf[kc][0], qf[kc][1], qf[kc][2], qf[kc][3],
                      bp[0], bp[4]);
            }
        }

        // ---- bias + row max ----
        float mx0 = -INFINITY, mx1 = -INFINITY;
#pragma unroll
        for (int nt = 0; nt < 8; nt++) {
            const int col0 = kt * 64 + nt * 8 + 2 * t;
            const int ki = col0 >> 5;
            const int kj = col0 & 31;
            s[nt].x += __ldg(&rel_bias[((qi0 - ki + 31) * 63 + (qj0 - kj + 31)) * NHEAD + h]);
            s[nt].y += __ldg(&rel_bias[((qi0 - ki + 31) * 63 + (qj0 - kj + 30)) * NHEAD + h]);
            s[nt].z += __ldg(&rel_bias[((qi1 - ki + 31) * 63 + (qj1 - kj + 31)) * NHEAD + h]);
            s[nt].w += __ldg(&rel_bias[((qi1 - ki + 31) * 63 + (qj1 - kj + 30)) * NHEAD + h]);
            mx0 = fmaxf(mx0, fmaxf(s[nt].x, s[nt].y));
            mx1 = fmaxf(mx1, fmaxf(s[nt].z, s[nt].w));
        }
        mx0 = fmaxf(mx0, __shfl_xor_sync(0xffffffffu, mx0, 1));
        mx0 = fmaxf(mx0, __shfl_xor_sync(0xffffffffu, mx0, 2));
        mx1 = fmaxf(mx1, __shfl_xor_sync(0xffffffffu, mx1, 1));
        mx1 = fmaxf(mx1, __shfl_xor_sync(0xffffffffu, mx1, 2));

        const float mn0 = fmaxf(m0, mx0);
        const float mn1 = fmaxf(m1, mx1);
        const float al0 = __expf(m0 - mn0);
        const float al1 = __expf(m1 - mn1);
        float rs0 = 0.f, rs1 = 0.f;
#pragma unroll
        for (int nt = 0; nt < 8; nt++) {
            s[nt].x = __expf(s[nt].x - mn0);
            s[nt].y = __expf(s[nt].y - mn0);
            s[nt].z = __expf(s[nt].z - mn1);
            s[nt].w = __expf(s[nt].w - mn1);
            rs0 += s[nt].x + s[nt].y;
            rs1 += s[nt].z + s[nt].w;
            o[nt].x *= al0; o[nt].y *= al0;
            o[nt].z *= al1; o[nt].w *= al1;
        }
        rs0 += __shfl_xor_sync(0xffffffffu, rs0, 1);
        rs0 += __shfl_xor_sync(0xffffffffu, rs0, 2);
        rs1 += __shfl_xor_sync(0xffffffffu, rs1, 1);
        rs1 += __shfl_xor_sync(0xffffffffu, rs1, 2);
        l0 = l0 * al0 + rs0; m0 = mn0;
        l1 = l1 * al1 + rs1; m1 = mn1;

        // ---- P: C-frag -> f16 A-frag, pure register pack ----
        uint32_t pa[4][4];
#pragma unroll
        for (int kc = 0; kc < 4; kc++) {
            pa[kc][0] = h2pack(s[2*kc].x,   s[2*kc].y);
            pa[kc][1] = h2pack(s[2*kc].z,   s[2*kc].w);
            pa[kc][2] = h2pack(s[2*kc+1].x, s[2*kc+1].y);
            pa[kc][3] = h2pack(s[2*kc+1].z, s[2*kc+1].w);
        }

        // ---- O += P V ----
#pragma unroll
        for (int kc = 0; kc < 4; kc++) {
#pragma unroll
            for (int nt = 0; nt < 8; nt++) {
                const uint32_t* bp = Vb + (nt * 8 + g) * KW + kc * 8 + t;
                mma16(o[nt], pa[kc][0], pa[kc][1], pa[kc][2], pa[kc][3],
                      bp[0], bp[4]);
            }
        }
        __syncthreads();   // all warps done with this buffer before re-issue
    }

    // ---- epilogue ----
    const float inv0 = 1.f / l0;
    const float inv1 = 1.f / l1;
    float* out0 = out + (size_t)(b * NTOK + qrow0) * CDIM + h * HDIM;
    float* out1 = out + (size_t)(b * NTOK + qrow0 + 8) * CDIM + h * HDIM;
#pragma unroll
    for (int nt = 0; nt < 8; nt++) {
        const int dd = nt * 8 + 2 * t;
        *(float2*)(out0 + dd) = make_float2(o[nt].x * inv0, o[nt].y * inv0);
        *(float2*)(out1 + dd) = make_float2(o[nt].z * inv1, o[nt].w * inv1);
    }
}

// ============================================================================
extern "C" void kernel_launch(void* const* d_in, const int* in_sizes, int n_in,
                              void* d_out, int out_size)
{
    const float* x        = (const float*)d_in[0];
    const float* Wq       = (const float*)d_in[1];
    const float* bq       = (const float*)d_in[2];
    const float* Wkv      = (const float*)d_in[3];
    const float* bkv      = (const float*)d_in[4];
    const float* rel_bias = (const float*)d_in[5];
    float* out = (float*)d_out;

    qkv_tc<<<dim3(NTOTC / 128, MROWS / 128), 256>>>(x, Wq, bq, Wkv, bkv);
    flash_tc<<<dim3(8, BATCH * NHEAD), 256>>>(rel_bias, out);
}

// round 7
// speedup vs baseline: 3.0889x; 1.4877x over previous
#include <cuda_runtime.h>
#include <cuda_fp16.h>
#include <math.h>
#include <stdint.h>

#define BATCH 8
#define NTOK  1024
#define CDIM  768
#define NHEAD 12
#define HDIM  64
#define NTOTC 2304
#define MROWS 8192
#define L2E   1.44269504f

// -------- device-global scratch --------
__device__ __align__(16) __half g_xh[MROWS * CDIM];          // fp16 x
__device__ __align__(16) __half g_wh[NTOTC * CDIM];          // fp16 [Wq; Wkv]
__device__ __align__(16) float  g_bias2[3969 * NHEAD];       // rel_bias * log2e
__device__ __align__(16) __half g_q [BATCH * NHEAD * NTOK * HDIM];  // pre-scaled
__device__ __align__(16) __half g_k [BATCH * NHEAD * NTOK * HDIM];
__device__ __align__(16) __half g_vT[BATCH * NHEAD * HDIM * NTOK];  // [bh][dim][tok]

// ============================================================================
// helpers
// ============================================================================
__device__ __forceinline__ uint32_t smem_u32(const void* p) {
    uint32_t a;
    asm("{ .reg .u64 t; cvta.to.shared.u64 t, %1; cvt.u32.u64 %0, t; }"
        : "=r"(a) : "l"(p));
    return a;
}
__device__ __forceinline__ uint32_t h2pack(float a, float b) {
    __half2 h = __floats2half2_rn(a, b);
    return *reinterpret_cast<uint32_t*>(&h);
}
__device__ __forceinline__ float ex2(float x) {
    float r;
    asm("ex2.approx.f32 %0, %1;" : "=f"(r) : "f"(x));
    return r;
}
__device__ __forceinline__ void mma16(float4& d,
                                      uint32_t a0, uint32_t a1, uint32_t a2, uint32_t a3,
                                      uint32_t b0, uint32_t b1) {
    asm volatile(
        "mma.sync.aligned.m16n8k16.row.col.f32.f16.f16.f32 "
        "{%0,%1,%2,%3}, {%4,%5,%6,%7}, {%8,%9}, {%0,%1,%2,%3};"
        : "+f"(d.x), "+f"(d.y), "+f"(d.z), "+f"(d.w)
        : "r"(a0), "r"(a1), "r"(a2), "r"(a3), "r"(b0), "r"(b1));
}
__device__ __forceinline__ void ldsm4(uint32_t* r, uint32_t a) {
    asm volatile("ldmatrix.sync.aligned.m8n8.x4.shared.b16 {%0,%1,%2,%3}, [%4];"
                 : "=r"(r[0]), "=r"(r[1]), "=r"(r[2]), "=r"(r[3]) : "r"(a));
}
__device__ __forceinline__ void cpasync16(uint32_t saddr, const void* gptr) {
    asm volatile("cp.async.cg.shared.global [%0], [%1], 16;"
                 :: "r"(saddr), "l"(gptr) : "memory");
}
#define CP_COMMIT() asm volatile("cp.async.commit_group;" ::: "memory")
#define CP_WAIT0()  asm volatile("cp.async.wait_group 0;" ::: "memory")

// ============================================================================
// Kernel 0: one-shot conversions (x->fp16, W->fp16, bias*log2e)
// ============================================================================
#define NX4 1572864   // 8192*768/4
#define NW4 442368    // 2304*768/4
#define NWQ4 147456   // 768*768/4
#define NB4 11907     // 47628/4
#define PREP_BLOCKS ((NX4 + NW4 + NB4 + 255) / 256)

__global__ __launch_bounds__(256)
void prep(const float* __restrict__ x, const float* __restrict__ Wq,
          const float* __restrict__ Wkv, const float* __restrict__ rb)
{
    const int idx = blockIdx.x * 256 + threadIdx.x;
    if (idx < NX4) {
        float4 v = __ldg((const float4*)x + idx);
        ((uint2*)g_xh)[idx] = make_uint2(h2pack(v.x, v.y), h2pack(v.z, v.w));
    } else if (idx < NX4 + NW4) {
        const int j = idx - NX4;
        const float4* src = (j < NWQ4) ? ((const float4*)Wq + j)
                                       : ((const float4*)Wkv + (j - NWQ4));
        float4 v = __ldg(src);
        ((uint2*)g_wh)[j] = make_uint2(h2pack(v.x, v.y), h2pack(v.z, v.w));
    } else if (idx < NX4 + NW4 + NB4) {
        const int j = idx - NX4 - NW4;
        float4 v = __ldg((const float4*)rb + j);
        ((float4*)g_bias2)[j] = make_float4(v.x * L2E, v.y * L2E, v.z * L2E, v.w * L2E);
    }
}

// ============================================================================
// Kernel 1: QKV projection, fp16 m16n8k16, cp.async 2-stage, ldmatrix frags.
// CTA 128x128, K=64 chunks x12, 8 warps (4M x 2N).
// ============================================================================
#define QSTAGE 36864u   // bytes per stage (A 18432 + B 18432), row stride 36 words
#define QKV_SMEM (2 * QSTAGE)

__global__ __launch_bounds__(256, 2)
void qkv_tc(const float* __restrict__ bq, const float* __restrict__ bkv)
{
    extern __shared__ __align__(16) char qraw[];
    const uint32_t sbq = smem_u32(qraw);

    const int tid  = threadIdx.x;
    const int wid  = tid >> 5;
    const int lane = tid & 31;
    const int g    = lane >> 2;
    const int tig  = lane & 3;
    const int mBase = blockIdx.y * 128;
    const int nBase = blockIdx.x * 128;
    const int wm = (wid >> 1) * 32;
    const int wn = (wid & 1) * 64;

    const __half* xh = g_xh;
    const __half* wh = g_wh;

    // per-lane ldmatrix offsets
    const int mA = lane >> 3;
    const uint32_t aoff = ((uint32_t)(wm + (mA & 1) * 8 + (lane & 7)) * 36
                           + (uint32_t)(mA >> 1) * 4) * 4;
    const uint32_t boff = ((uint32_t)(wn + (mA >> 1) * 8 + (lane & 7)) * 36
                           + (uint32_t)(mA & 1) * 4) * 4;

#define QISSUE(ch_, s_)                                                          \
    do {                                                                         \
        const uint32_t ad = sbq + (uint32_t)(s_) * QSTAGE;                       \
        const uint32_t bd = ad + 18432u;                                         \
        _Pragma("unroll")                                                        \
        for (int i = 0; i < 4; i++) {                                            \
            const int c = tid + i * 256;                                         \
            const int row = c >> 3, ii = c & 7;                                  \
            cpasync16(ad + (uint32_t)(row * 36 + ii * 4) * 4,                    \
                      xh + (size_t)(mBase + row) * CDIM + (ch_) * 64 + ii * 8);  \
            cpasync16(bd + (uint32_t)(row * 36 + ii * 4) * 4,                    \
                      wh + (size_t)(nBase + row) * CDIM + (ch_) * 64 + ii * 8);  \
        }                                                                        \
    } while (0)

    float4 dacc[2][8];
#pragma unroll
    for (int mt = 0; mt < 2; mt++)
#pragma unroll
        for (int nt = 0; nt < 8; nt++) dacc[mt][nt] = make_float4(0.f, 0.f, 0.f, 0.f);

    QISSUE(0, 0);
    CP_COMMIT();

    for (int ch = 0; ch < 12; ch++) {
        CP_WAIT0();
        __syncthreads();
        if (ch < 11) { QISSUE(ch + 1, (ch + 1) & 1); CP_COMMIT(); }

        const uint32_t Aad = sbq + (uint32_t)(ch & 1) * QSTAGE;
        const uint32_t Bad = Aad + 18432u;
#pragma unroll
        for (int kc = 0; kc < 4; kc++) {
            uint32_t a0[4], a1[4];
            ldsm4(a0, Aad + aoff + kc * 32);
            ldsm4(a1, Aad + aoff + 2304 + kc * 32);   // mt=1: +16 rows
#pragma unroll
            for (int p = 0; p < 4; p++) {
                uint32_t bf[4];
                ldsm4(bf, Bad + boff + p * 2304 + kc * 32);
                mma16(dacc[0][2*p],   a0[0], a0[1], a0[2], a0[3], bf[0], bf[1]);
                mma16(dacc[0][2*p+1], a0[0], a0[1], a0[2], a0[3], bf[2], bf[3]);
                mma16(dacc[1][2*p],   a1[0], a1[1], a1[2], a1[3], bf[0], bf[1]);
                mma16(dacc[1][2*p+1], a1[0], a1[1], a1[2], a1[3], bf[2], bf[3]);
            }
        }
    }

    const int bidx = mBase >> 10;

    if (nBase < 1536) {
        // ---- Q or K: direct fp16 row-major stores ----
        const int cb = nBase + wn;
        const bool isQ = (cb < 768);
        const float mul = isQ ? (0.125f * L2E) : 1.f;
        const float* brow = isQ ? (bq + cb) : (bkv + (cb - 768));
        __half* dst = isQ ? g_q : g_k;
        const int hh = (cb % 768) >> 6;
        const int bh = bidx * NHEAD + hh;
#pragma unroll
        for (int mt = 0; mt < 2; mt++) {
#pragma unroll
            for (int rr = 0; rr < 2; rr++) {
                const int row = mBase + wm + mt * 16 + g + rr * 8;
                const int tok = row & 1023;
                uint32_t* orow = (uint32_t*)(dst + (size_t)(bh * NTOK + tok) * HDIM);
#pragma unroll
                for (int nt = 0; nt < 8; nt++) {
                    const int dd = nt * 8 + 2 * tig;
                    float v0, v1;
                    if (rr == 0) { v0 = dacc[mt][nt].x; v1 = dacc[mt][nt].y; }
                    else         { v0 = dacc[mt][nt].z; v1 = dacc[mt][nt].w; }
                    v0 = (v0 + __ldg(brow + dd)) * mul;
                    v1 = (v1 + __ldg(brow + dd + 1)) * mul;
                    orow[dd >> 1] = h2pack(v0, v1);
                }
            }
        }
    } else {
        // ---- V: transpose via smem, write g_vT[bh][dim][tok] ----
        __half* Vt = (__half*)qraw;   // [64][136] halves = 17408 B
#pragma unroll
        for (int p = 0; p < 2; p++) {
            if (wn == p * 64) {
                const float* brow = bkv + (nBase + wn - 768);
#pragma unroll
                for (int mt = 0; mt < 2; mt++) {
#pragma unroll
                    for (int rr = 0; rr < 2; rr++) {
                        const int tokl = wm + mt * 16 + g + rr * 8;
#pragma unroll
                        for (int nt = 0; nt < 8; nt++) {
                            const int dd = nt * 8 + 2 * tig;
                            float v0, v1;
                            if (rr == 0) { v0 = dacc[mt][nt].x; v1 = dacc[mt][nt].y; }
                            else         { v0 = dacc[mt][nt].z; v1 = dacc[mt][nt].w; }
                            Vt[dd * 136 + tokl]       = __float2half_rn(v0 + __ldg(brow + dd));
                            Vt[(dd + 1) * 136 + tokl] = __float2half_rn(v1 + __ldg(brow + dd + 1));
                        }
                    }
                }
            }
            __syncthreads();
            const int hp = (nBase + p * 64 - 1536) >> 6;
            const int bh_p = bidx * NHEAD + hp;
            const int d = tid >> 2;
            const int tok0 = (tid & 3) * 32;
            const uint32_t* vtw = (const uint32_t*)Vt;
            uint32_t* odst = (uint32_t*)(g_vT + (size_t)(bh_p * HDIM + d) * NTOK
                                         + (mBase & 1023) + tok0);
#pragma unroll
            for (int i = 0; i < 4; i++) {
                uint4 val = *(const uint4*)(vtw + d * 68 + (tok0 >> 1) + 4 * i);
                *(uint4*)(odst + 4 * i) = val;
            }
            __syncthreads();
        }
    }
}

// ============================================================================
// Kernel 2: flash attention, fp16 m16n8k16, cp.async 2-stage (1 barrier/tile),
// ldmatrix B-frags, ex2 softmax (Q and bias pre-scaled by log2e).
// ============================================================================
#define KW 36   // smem row stride in u32 words

__global__ __launch_bounds__(256, 2)
void flash_tc(float* __restrict__ out)
{
    __shared__ __align__(16) uint32_t fsm[4 * 64 * KW];   // 36864 B

    const int tid  = threadIdx.x;
    const int wid  = tid >> 5;
    const int lane = tid & 31;
    const int g    = lane >> 2;
    const int t    = lane & 3;
    const int qt   = blockIdx.x;
    const int bh   = blockIdx.y;
    const int b    = bh / NHEAD;
    const int h    = bh % NHEAD;

    const uint32_t sb = smem_u32(fsm);
    const __half* kbh = g_k  + (size_t)bh * (NTOK * HDIM);
    const __half* vbh = g_vT + (size_t)bh * (HDIM * NTOK);

    // Q A-fragments, register resident
    const int qrow0 = qt * 128 + wid * 16 + g;
    const uint32_t* qw = (const uint32_t*)g_q + (size_t)(bh * NTOK + qrow0) * 32;
    uint32_t qf[4][4];
#pragma unroll
    for (int kc = 0; kc < 4; kc++) {
        qf[kc][0] = __ldg(qw + kc * 8 + t);
        qf[kc][1] = __ldg(qw + 256 + kc * 8 + t);
        qf[kc][2] = __ldg(qw + kc * 8 + t + 4);
        qf[kc][3] = __ldg(qw + 256 + kc * 8 + t + 4);
    }

    // per-lane ldmatrix offset for K/V B-frags
    const int mA = lane >> 3;
    const uint32_t kvoff = ((uint32_t)((mA >> 1) * 8 + (lane & 7)) * KW
                            + (uint32_t)(mA & 1) * 4) * 4;

    const int qi0 = qrow0 >> 5,       qj0 = qrow0 & 31;
    const int qi1 = (qrow0 + 8) >> 5, qj1 = (qrow0 + 8) & 31;

    float4 o[8];
#pragma unroll
    for (int nt = 0; nt < 8; nt++) o[nt] = make_float4(0.f, 0.f, 0.f, 0.f);
    float m0 = -INFINITY, m1 = -INFINITY, l0 = 0.f, l1 = 0.f;

#define ISSUE_TILE(kt_, bsel_)                                                  \
    do {                                                                        \
        const uint32_t kd = sb + (uint32_t)(bsel_) * (64 * KW * 4);             \
        const uint32_t vd = kd + 2 * (64 * KW * 4);                             \
        _Pragma("unroll")                                                       \
        for (int c = tid; c < 512; c += 256) {                                  \
            const int row = c >> 3, ii = c & 7;                                 \
            cpasync16(kd + (uint32_t)(row * KW + ii * 4) * 4,                   \
                      kbh + ((kt_) * 64 + row) * 64 + ii * 8);                  \
            cpasync16(vd + (uint32_t)(row * KW + ii * 4) * 4,                   \
                      vbh + row * NTOK + (kt_) * 64 + ii * 8);                  \
        }                                                                       \
    } while (0)

    ISSUE_TILE(0, 0);
    CP_COMMIT();

    for (int kt = 0; kt < 16; kt++) {
        CP_WAIT0();
        __syncthreads();
        if (kt < 15) { ISSUE_TILE(kt + 1, (kt + 1) & 1); CP_COMMIT(); }

        const uint32_t Kad = sb + (uint32_t)(kt & 1) * (64 * KW * 4);
        const uint32_t Vad = Kad + 2 * (64 * KW * 4);

        // ---- S = Q K^T ----
        float4 s[8];
#pragma unroll
        for (int nt = 0; nt < 8; nt++) s[nt] = make_float4(0.f, 0.f, 0.f, 0.f);
#pragma unroll
        for (int kc = 0; kc < 4; kc++) {
#pragma unroll
            for (int p = 0; p < 4; p++) {
                uint32_t bf[4];
                ldsm4(bf, Kad + kvoff + p * 2304 + kc * 32);
                mma16(s[2*p],   qf[kc][0], qf[kc][1], qf[kc][2], qf[kc][3], bf[0], bf[1]);
                mma16(s[2*p+1], qf[kc][0], qf[kc][1], qf[kc][2], qf[kc][3], bf[2], bf[3]);
            }
        }

        // ---- bias (pre-scaled by log2e) + row max ----
        float mx0 = -INFINITY, mx1 = -INFINITY;
#pragma unroll
        for (int nt = 0; nt < 8; nt++) {
            const int col0 = kt * 64 + nt * 8 + 2 * t;
            const int ki = col0 >> 5;
            const int kj = col0 & 31;
            s[nt].x += __ldg(&g_bias2[((qi0 - ki + 31) * 63 + (qj0 - kj + 31)) * NHEAD + h]);
            s[nt].y += __ldg(&g_bias2[((qi0 - ki + 31) * 63 + (qj0 - kj + 30)) * NHEAD + h]);
            s[nt].z += __ldg(&g_bias2[((qi1 - ki + 31) * 63 + (qj1 - kj + 31)) * NHEAD + h]);
            s[nt].w += __ldg(&g_bias2[((qi1 - ki + 31) * 63 + (qj1 - kj + 30)) * NHEAD + h]);
            mx0 = fmaxf(mx0, fmaxf(s[nt].x, s[nt].y));
            mx1 = fmaxf(mx1, fmaxf(s[nt].z, s[nt].w));
        }
        mx0 = fmaxf(mx0, __shfl_xor_sync(0xffffffffu, mx0, 1));
        mx0 = fmaxf(mx0, __shfl_xor_sync(0xffffffffu, mx0, 2));
        mx1 = fmaxf(mx1, __shfl_xor_sync(0xffffffffu, mx1, 1));
        mx1 = fmaxf(mx1, __shfl_xor_sync(0xffffffffu, mx1, 2));

        const float mn0 = fmaxf(m0, mx0);
        const float mn1 = fmaxf(m1, mx1);
        const float al0 = ex2(m0 - mn0);
        const float al1 = ex2(m1 - mn1);
        float rs0 = 0.f, rs1 = 0.f;
#pragma unroll
        for (int nt = 0; nt < 8; nt++) {
            s[nt].x = ex2(s[nt].x - mn0);
            s[nt].y = ex2(s[nt].y - mn0);
            s[nt].z = ex2(s[nt].z - mn1);
            s[nt].w = ex2(s[nt].w - mn1);
            rs0 += s[nt].x + s[nt].y;
            rs1 += s[nt].z + s[nt].w;
            o[nt].x *= al0; o[nt].y *= al0;
            o[nt].z *= al1; o[nt].w *= al1;
        }
        rs0 += __shfl_xor_sync(0xffffffffu, rs0, 1);
        rs0 += __shfl_xor_sync(0xffffffffu, rs0, 2);
        rs1 += __shfl_xor_sync(0xffffffffu, rs1, 1);
        rs1 += __shfl_xor_sync(0xffffffffu, rs1, 2);
        l0 = l0 * al0 + rs0; m0 = mn0;
        l1 = l1 * al1 + rs1; m1 = mn1;

        // ---- P: C-frag -> f16 A-frag, pure register pack ----
        uint32_t pa[4][4];
#pragma unroll
        for (int kc = 0; kc < 4; kc++) {
            pa[kc][0] = h2pack(s[2*kc].x,   s[2*kc].y);
            pa[kc][1] = h2pack(s[2*kc].z,   s[2*kc].w);
            pa[kc][2] = h2pack(s[2*kc+1].x, s[2*kc+1].y);
            pa[kc][3] = h2pack(s[2*kc+1].z, s[2*kc+1].w);
        }

        // ---- O += P V ----
#pragma unroll
        for (int kc = 0; kc < 4; kc++) {
#pragma unroll
            for (int p = 0; p < 4; p++) {
                uint32_t bf[4];
                ldsm4(bf, Vad + kvoff + p * 2304 + kc * 32);
                mma16(o[2*p],   pa[kc][0], pa[kc][1], pa[kc][2], pa[kc][3], bf[0], bf[1]);
                mma16(o[2*p+1], pa[kc][0], pa[kc][1], pa[kc][2], pa[kc][3], bf[2], bf[3]);
            }
        }
    }

    // ---- epilogue ----
    const float inv0 = 1.f / l0;
    const float inv1 = 1.f / l1;
    float* out0 = out + (size_t)(b * NTOK + qrow0) * CDIM + h * HDIM;
    float* out1 = out + (size_t)(b * NTOK + qrow0 + 8) * CDIM + h * HDIM;
#pragma unroll
    for (int nt = 0; nt < 8; nt++) {
        const int dd = nt * 8 + 2 * t;
        *(float2*)(out0 + dd) = make_float2(o[nt].x * inv0, o[nt].y * inv0);
        *(float2*)(out1 + dd) = make_float2(o[nt].z * inv1, o[nt].w * inv1);
    }
}

// ============================================================================
extern "C" void kernel_launch(void* const* d_in, const int* in_sizes, int n_in,
                              void* d_out, int out_size)
{
    const float* x        = (const float*)d_in[0];
    const float* Wq       = (const float*)d_in[1];
    const float* bq       = (const float*)d_in[2];
    const float* Wkv      = (const float*)d_in[3];
    const float* bkv      = (const float*)d_in[4];
    const float* rel_bias = (const float*)d_in[5];
    float* out = (float*)d_out;

    prep<<<PREP_BLOCKS, 256>>>(x, Wq, Wkv, rel_bias);

    cudaFuncSetAttribute(qkv_tc, cudaFuncAttributeMaxDynamicSharedMemorySize,
                         QKV_SMEM);
    qkv_tc<<<dim3(NTOTC / 128, MROWS / 128), 256, QKV_SMEM>>>(bq, bkv);

    flash_tc<<<dim3(8, BATCH * NHEAD), 256>>>(out);
}

// round 8
// speedup vs baseline: 3.1279x; 1.0126x over previous
#include <cuda_runtime.h>
#include <cuda_fp16.h>
#include <math.h>
#include <stdint.h>

#define BATCH 8
#define NTOK  1024
#define CDIM  768
#define NHEAD 12
#define HDIM  64
#define NTOTC 2304
#define MROWS 8192
#define L2E   1.44269504f

// -------- device-global scratch --------
__device__ __align__(16) __half g_xh[MROWS * CDIM];          // fp16 x
__device__ __align__(16) __half g_wh[NTOTC * CDIM];          // fp16 [Wq; Wkv]
__device__ __align__(16) float  g_biasT[NHEAD * 4096];       // [h][(dqi+31)*64+(dqj+31)] * log2e
__device__ __align__(16) __half g_q [BATCH * NHEAD * NTOK * HDIM];  // pre-scaled by 0.125*log2e
__device__ __align__(16) __half g_k [BATCH * NHEAD * NTOK * HDIM];
__device__ __align__(16) __half g_vT[BATCH * NHEAD * HDIM * NTOK];  // [bh][dim][tok]

// ============================================================================
// helpers
// ============================================================================
__device__ __forceinline__ uint32_t smem_u32(const void* p) {
    uint32_t a;
    asm("{ .reg .u64 t; cvta.to.shared.u64 t, %1; cvt.u32.u64 %0, t; }"
        : "=r"(a) : "l"(p));
    return a;
}
__device__ __forceinline__ uint32_t h2pack(float a, float b) {
    __half2 h = __floats2half2_rn(a, b);
    return *reinterpret_cast<uint32_t*>(&h);
}
__device__ __forceinline__ float ex2(float x) {
    float r;
    asm("ex2.approx.f32 %0, %1;" : "=f"(r) : "f"(x));
    return r;
}
__device__ __forceinline__ void mma16(float4& d,
                                      uint32_t a0, uint32_t a1, uint32_t a2, uint32_t a3,
                                      uint32_t b0, uint32_t b1) {
    asm volatile(
        "mma.sync.aligned.m16n8k16.row.col.f32.f16.f16.f32 "
        "{%0,%1,%2,%3}, {%4,%5,%6,%7}, {%8,%9}, {%0,%1,%2,%3};"
        : "+f"(d.x), "+f"(d.y), "+f"(d.z), "+f"(d.w)
        : "r"(a0), "r"(a1), "r"(a2), "r"(a3), "r"(b0), "r"(b1));
}
__device__ __forceinline__ void ldsm4(uint32_t* r, uint32_t a) {
    asm volatile("ldmatrix.sync.aligned.m8n8.x4.shared.b16 {%0,%1,%2,%3}, [%4];"
                 : "=r"(r[0]), "=r"(r[1]), "=r"(r[2]), "=r"(r[3]) : "r"(a));
}
__device__ __forceinline__ void cpasync16(uint32_t saddr, const void* gptr) {
    asm volatile("cp.async.cg.shared.global [%0], [%1], 16;"
                 :: "r"(saddr), "l"(gptr) : "memory");
}
#define CP_COMMIT() asm volatile("cp.async.commit_group;" ::: "memory")
#define CP_WAIT0()  asm volatile("cp.async.wait_group 0;" ::: "memory")
#define CP_WAIT1()  asm volatile("cp.async.wait_group 1;" ::: "memory")

// ============================================================================
// Kernel 0: one-shot conversions (x->fp16, W->fp16, bias transpose+scale)
// ============================================================================
#define NX4 1572864   // 8192*768/4
#define NW4 442368    // 2304*768/4
#define NWQ4 147456   // 768*768/4
#define NBT 47628     // 63*63*12 scalars
#define PREP_BLOCKS ((NX4 + NW4 + NBT + 255) / 256)

__global__ __launch_bounds__(256)
void prep(const float* __restrict__ x, const float* __restrict__ Wq,
          const float* __restrict__ Wkv, const float* __restrict__ rb)
{
    const int idx = blockIdx.x * 256 + threadIdx.x;
    if (idx < NX4) {
        float4 v = __ldg((const float4*)x + idx);
        ((uint2*)g_xh)[idx] = make_uint2(h2pack(v.x, v.y), h2pack(v.z, v.w));
    } else if (idx < NX4 + NW4) {
        const int j = idx - NX4;
        const float4* src = (j < NWQ4) ? ((const float4*)Wq + j)
                                       : ((const float4*)Wkv + (j - NWQ4));
        float4 v = __ldg(src);
        ((uint2*)g_wh)[j] = make_uint2(h2pack(v.x, v.y), h2pack(v.z, v.w));
    } else if (idx < NX4 + NW4 + NBT) {
        // rb layout: [(r*63+c)][12]; write g_biasT[h][r*64+c] = rb*log2e
        const int j  = idx - NX4 - NW4;          // = rc*12 + h
        const int rc = j / 12;
        const int h  = j - rc * 12;
        const int r  = rc / 63;
        const int c  = rc - r * 63;
        g_biasT[h * 4096 + r * 64 + c] = __ldg(rb + j) * L2E;
    }
}

// ============================================================================
// Kernel 1: QKV projection, fp16 m16n8k16, cp.async 2-stage, ldmatrix frags.
// ============================================================================
#define QSTAGE 36864u
#define QKV_SMEM (2 * QSTAGE)

__global__ __launch_bounds__(256, 2)
void qkv_tc(const float* __restrict__ bq, const float* __restrict__ bkv)
{
    extern __shared__ __align__(16) char qraw[];
    const uint32_t sbq = smem_u32(qraw);

    const int tid  = threadIdx.x;
    const int wid  = tid >> 5;
    const int lane = tid & 31;
    const int g    = lane >> 2;
    const int tig  = lane & 3;
    const int mBase = blockIdx.y * 128;
    const int nBase = blockIdx.x * 128;
    const int wm = (wid >> 1) * 32;
    const int wn = (wid & 1) * 64;

    const __half* xh = g_xh;
    const __half* wh = g_wh;

    const int mA = lane >> 3;
    const uint32_t aoff = ((uint32_t)(wm + (mA & 1) * 8 + (lane & 7)) * 36
                           + (uint32_t)(mA >> 1) * 4) * 4;
    const uint32_t boff = ((uint32_t)(wn + (mA >> 1) * 8 + (lane & 7)) * 36
                           + (uint32_t)(mA & 1) * 4) * 4;

#define QISSUE(ch_, s_)                                                          \
    do {                                                                         \
        const uint32_t ad = sbq + (uint32_t)(s_) * QSTAGE;                       \
        const uint32_t bd = ad + 18432u;                                         \
        _Pragma("unroll")                                                        \
        for (int i = 0; i < 4; i++) {                                            \
            const int c = tid + i * 256;                                         \
            const int row = c >> 3, ii = c & 7;                                  \
            cpasync16(ad + (uint32_t)(row * 36 + ii * 4) * 4,                    \
                      xh + (size_t)(mBase + row) * CDIM + (ch_) * 64 + ii * 8);  \
            cpasync16(bd + (uint32_t)(row * 36 + ii * 4) * 4,                    \
                      wh + (size_t)(nBase + row) * CDIM + (ch_) * 64 + ii * 8);  \
        }                                                                        \
    } while (0)

    float4 dacc[2][8];
#pragma unroll
    for (int mt = 0; mt < 2; mt++)
#pragma unroll
        for (int nt = 0; nt < 8; nt++) dacc[mt][nt] = make_float4(0.f, 0.f, 0.f, 0.f);

    QISSUE(0, 0);
    CP_COMMIT();

    for (int ch = 0; ch < 12; ch++) {
        CP_WAIT0();
        __syncthreads();
        if (ch < 11) { QISSUE(ch + 1, (ch + 1) & 1); CP_COMMIT(); }

        const uint32_t Aad = sbq + (uint32_t)(ch & 1) * QSTAGE;
        const uint32_t Bad = Aad + 18432u;
#pragma unroll
        for (int kc = 0; kc < 4; kc++) {
            uint32_t a0[4], a1[4];
            ldsm4(a0, Aad + aoff + kc * 32);
            ldsm4(a1, Aad + aoff + 2304 + kc * 32);
#pragma unroll
            for (int p = 0; p < 4; p++) {
                uint32_t bf[4];
                ldsm4(bf, Bad + boff + p * 2304 + kc * 32);
                mma16(dacc[0][2*p],   a0[0], a0[1], a0[2], a0[3], bf[0], bf[1]);
                mma16(dacc[0][2*p+1], a0[0], a0[1], a0[2], a0[3], bf[2], bf[3]);
                mma16(dacc[1][2*p],   a1[0], a1[1], a1[2], a1[3], bf[0], bf[1]);
                mma16(dacc[1][2*p+1], a1[0], a1[1], a1[2], a1[3], bf[2], bf[3]);
            }
        }
    }

    const int bidx = mBase >> 10;

    if (nBase < 1536) {
        const int cb = nBase + wn;
        const bool isQ = (cb < 768);
        const float mul = isQ ? (0.125f * L2E) : 1.f;
        const float* brow = isQ ? (bq + cb) : (bkv + (cb - 768));
        __half* dst = isQ ? g_q : g_k;
        const int hh = (cb % 768) >> 6;
        const int bh = bidx * NHEAD + hh;
#pragma unroll
        for (int mt = 0; mt < 2; mt++) {
#pragma unroll
            for (int rr = 0; rr < 2; rr++) {
                const int row = mBase + wm + mt * 16 + g + rr * 8;
                const int tok = row & 1023;
                uint32_t* orow = (uint32_t*)(dst + (size_t)(bh * NTOK + tok) * HDIM);
#pragma unroll
                for (int nt = 0; nt < 8; nt++) {
                    const int dd = nt * 8 + 2 * tig;
                    float v0, v1;
                    if (rr == 0) { v0 = dacc[mt][nt].x; v1 = dacc[mt][nt].y; }
                    else         { v0 = dacc[mt][nt].z; v1 = dacc[mt][nt].w; }
                    v0 = (v0 + __ldg(brow + dd)) * mul;
                    v1 = (v1 + __ldg(brow + dd + 1)) * mul;
                    orow[dd >> 1] = h2pack(v0, v1);
                }
            }
        }
    } else {
        __half* Vt = (__half*)qraw;   // [64][136] halves
#pragma unroll
        for (int p = 0; p < 2; p++) {
            if (wn == p * 64) {
                const float* brow = bkv + (nBase + wn - 768);
#pragma unroll
                for (int mt = 0; mt < 2; mt++) {
#pragma unroll
                    for (int rr = 0; rr < 2; rr++) {
                        const int tokl = wm + mt * 16 + g + rr * 8;
#pragma unroll
                        for (int nt = 0; nt < 8; nt++) {
                            const int dd = nt * 8 + 2 * tig;
                            float v0, v1;
                            if (rr == 0) { v0 = dacc[mt][nt].x; v1 = dacc[mt][nt].y; }
                            else         { v0 = dacc[mt][nt].z; v1 = dacc[mt][nt].w; }
                            Vt[dd * 136 + tokl]       = __float2half_rn(v0 + __ldg(brow + dd));
                            Vt[(dd + 1) * 136 + tokl] = __float2half_rn(v1 + __ldg(brow + dd + 1));
                        }
                    }
                }
            }
            __syncthreads();
            const int hp = (nBase + p * 64 - 1536) >> 6;
            const int bh_p = bidx * NHEAD + hp;
            const int d = tid >> 2;
            const int tok0 = (tid & 3) * 32;
            const uint32_t* vtw = (const uint32_t*)Vt;
            uint32_t* odst = (uint32_t*)(g_vT + (size_t)(bh_p * HDIM + d) * NTOK
                                         + (mBase & 1023) + tok0);
#pragma unroll
            for (int i = 0; i < 4; i++) {
                uint4 val = *(const uint4*)(vtw + d * 68 + (tok0 >> 1) + 4 * i);
                *(uint4*)(odst + 4 * i) = val;
            }
            __syncthreads();
        }
    }
}

// ============================================================================
// Kernel 2: flash attention, fp16 m16n8k16, 3-stage cp.async, ldmatrix frags,
// ex2 softmax, L1-resident transposed bias table.
// ============================================================================
#define KW 36                       // smem row stride in u32 words
#define FL_STAGE (2 * 64 * KW * 4)  // bytes per stage (K + V) = 18432
#define FL_SMEM  (3 * FL_STAGE)     // 55296

__global__ __launch_bounds__(256, 2)
void flash_tc(float* __restrict__ out)
{
    extern __shared__ __align__(16) uint32_t fsm[];

    const int tid  = threadIdx.x;
    const int wid  = tid >> 5;
    const int lane = tid & 31;
    const int g    = lane >> 2;
    const int t    = lane & 3;
    const int qt   = blockIdx.x;
    const int bh   = blockIdx.y;
    const int b    = bh / NHEAD;
    const int h    = bh % NHEAD;

    const uint32_t sb = smem_u32(fsm);
    const __half* kbh = g_k  + (size_t)bh * (NTOK * HDIM);
    const __half* vbh = g_vT + (size_t)bh * (HDIM * NTOK);
    const float* bt = g_biasT + h * 4096;

    // Q A-fragments, register resident
    const int qrow0 = qt * 128 + wid * 16 + g;
    const uint32_t* qw = (const uint32_t*)g_q + (size_t)(bh * NTOK + qrow0) * 32;
    uint32_t qf[4][4];
#pragma unroll
    for (int kc = 0; kc < 4; kc++) {
        qf[kc][0] = __ldg(qw + kc * 8 + t);
        qf[kc][1] = __ldg(qw + 256 + kc * 8 + t);
        qf[kc][2] = __ldg(qw + kc * 8 + t + 4);
        qf[kc][3] = __ldg(qw + 256 + kc * 8 + t + 4);
    }

    const int mA = lane >> 3;
    const uint32_t kvoff = ((uint32_t)((mA >> 1) * 8 + (lane & 7)) * KW
                            + (uint32_t)(mA & 1) * 4) * 4;

    const int qi0 = qrow0 >> 5,       qj0 = qrow0 & 31;
    const int qi1 = (qrow0 + 8) >> 5, qj1 = (qrow0 + 8) & 31;

    float4 o[8];
#pragma unroll
    for (int nt = 0; nt < 8; nt++) o[nt] = make_float4(0.f, 0.f, 0.f, 0.f);
    float m0 = -INFINITY, m1 = -INFINITY, l0 = 0.f, l1 = 0.f;

#define ISSUE_TILE(kt_, s_)                                                     \
    do {                                                                        \
        const uint32_t kd = sb + (uint32_t)(s_) * FL_STAGE;                     \
        const uint32_t vd = kd + (64 * KW * 4);                                 \
        _Pragma("unroll")                                                       \
        for (int c = tid; c < 512; c += 256) {                                  \
            const int row = c >> 3, ii = c & 7;                                 \
            cpasync16(kd + (uint32_t)(row * KW + ii * 4) * 4,                   \
                      kbh + ((kt_) * 64 + row) * 64 + ii * 8);                  \
            cpasync16(vd + (uint32_t)(row * KW + ii * 4) * 4,                   \
                      vbh + row * NTOK + (kt_) * 64 + ii * 8);                  \
        }                                                                       \
    } while (0)

    ISSUE_TILE(0, 0);
    CP_COMMIT();
    ISSUE_TILE(1, 1);
    CP_COMMIT();

    for (int kt = 0; kt < 16; kt++) {
        if (kt < 15) CP_WAIT1(); else CP_WAIT0();
        __syncthreads();
        if (kt < 14) {
            const int nx = kt + 2;
            ISSUE_TILE(nx, nx - (nx / 3) * 3);
            CP_COMMIT();
        }

        const int ss = kt - (kt / 3) * 3;
        const uint32_t Kad = sb + (uint32_t)ss * FL_STAGE;
        const uint32_t Vad = Kad + (64 * KW * 4);

        // ---- S = Q K^T ----
        float4 s[8];
#pragma unroll
        for (int nt = 0; nt < 8; nt++) s[nt] = make_float4(0.f, 0.f, 0.f, 0.f);
#pragma unroll
        for (int kc = 0; kc < 4; kc++) {
#pragma unroll
            for (int p = 0; p < 4; p++) {
                uint32_t bf[4];
                ldsm4(bf, Kad + kvoff + p * 2304 + kc * 32);
                mma16(s[2*p],   qf[kc][0], qf[kc][1], qf[kc][2], qf[kc][3], bf[0], bf[1]);
                mma16(s[2*p+1], qf[kc][0], qf[kc][1], qf[kc][2], qf[kc][3], bf[2], bf[3]);
            }
        }

        // ---- bias (transposed, L1-resident, pre-scaled) + row max ----
        float mx0 = -INFINITY, mx1 = -INFINITY;
#pragma unroll
        for (int nt = 0; nt < 8; nt++) {
            const int col0 = kt * 64 + nt * 8 + 2 * t;
            const int ki = col0 >> 5;
            const int kj = col0 & 31;
            const int b0i = (qi0 - ki + 31) * 64 + (qj0 - kj + 31);
            const int b1i = (qi1 - ki + 31) * 64 + (qj1 - kj + 31);
            s[nt].x += __ldg(bt + b0i);
            s[nt].y += __ldg(bt + b0i - 1);
            s[nt].z += __ldg(bt + b1i);
            s[nt].w += __ldg(bt + b1i - 1);
            mx0 = fmaxf(mx0, fmaxf(s[nt].x, s[nt].y));
            mx1 = fmaxf(mx1, fmaxf(s[nt].z, s[nt].w));
        }
        mx0 = fmaxf(mx0, __shfl_xor_sync(0xffffffffu, mx0, 1));
        mx0 = fmaxf(mx0, __shfl_xor_sync(0xffffffffu, mx0, 2));
        mx1 = fmaxf(mx1, __shfl_xor_sync(0xffffffffu, mx1, 1));
        mx1 = fmaxf(mx1, __shfl_xor_sync(0xffffffffu, mx1, 2));

        const float mn0 = fmaxf(m0, mx0);
        const float mn1 = fmaxf(m1, mx1);
        const float al0 = ex2(m0 - mn0);
        const float al1 = ex2(m1 - mn1);
        float rs0 = 0.f, rs1 = 0.f;
#pragma unroll
        for (int nt = 0; nt < 8; nt++) {
            s[nt].x = ex2(s[nt].x - mn0);
            s[nt].y = ex2(s[nt].y - mn0);
            s[nt].z = ex2(s[nt].z - mn1);
            s[nt].w = ex2(s[nt].w - mn1);
            rs0 += s[nt].x + s[nt].y;
            rs1 += s[nt].z + s[nt].w;
            o[nt].x *= al0; o[nt].y *= al0;
            o[nt].z *= al1; o[nt].w *= al1;
        }
        rs0 += __shfl_xor_sync(0xffffffffu, rs0, 1);
        rs0 += __shfl_xor_sync(0xffffffffu, rs0, 2);
        rs1 += __shfl_xor_sync(0xffffffffu, rs1, 1);
        rs1 += __shfl_xor_sync(0xffffffffu, rs1, 2);
        l0 = l0 * al0 + rs0; m0 = mn0;
        l1 = l1 * al1 + rs1; m1 = mn1;

        // ---- P: C-frag -> f16 A-frag register pack ----
        uint32_t pa[4][4];
#pragma unroll
        for (int kc = 0; kc < 4; kc++) {
            pa[kc][0] = h2pack(s[2*kc].x,   s[2*kc].y);
            pa[kc][1] = h2pack(s[2*kc].z,   s[2*kc].w);
            pa[kc][2] = h2pack(s[2*kc+1].x, s[2*kc+1].y);
            pa[kc][3] = h2pack(s[2*kc+1].z, s[2*kc+1].w);
        }

        // ---- O += P V ----
#pragma unroll
        for (int kc = 0; kc < 4; kc++) {
#pragma unroll
            for (int p = 0; p < 4; p++) {
                uint32_t bf[4];
                ldsm4(bf, Vad + kvoff + p * 2304 + kc * 32);
                mma16(o[2*p],   pa[kc][0], pa[kc][1], pa[kc][2], pa[kc][3], bf[0], bf[1]);
                mma16(o[2*p+1], pa[kc][0], pa[kc][1], pa[kc][2], pa[kc][3], bf[2], bf[3]);
            }
        }
    }

    // ---- epilogue ----
    const float inv0 = 1.f / l0;
    const float inv1 = 1.f / l1;
    float* out0 = out + (size_t)(b * NTOK + qrow0) * CDIM + h * HDIM;
    float* out1 = out + (size_t)(b * NTOK + qrow0 + 8) * CDIM + h * HDIM;
#pragma unroll
    for (int nt = 0; nt < 8; nt++) {
        const int dd = nt * 8 + 2 * t;
        *(float2*)(out0 + dd) = make_float2(o[nt].x * inv0, o[nt].y * inv0);
        *(float2*)(out1 + dd) = make_float2(o[nt].z * inv1, o[nt].w * inv1);
    }
}

// ============================================================================
extern "C" void kernel_launch(void* const* d_in, const int* in_sizes, int n_in,
                              void* d_out, int out_size)
{
    const float* x        = (const float*)d_in[0];
    const float* Wq       = (const float*)d_in[1];
    const float* bq       = (const float*)d_in[2];
    const float* Wkv      = (const float*)d_in[3];
    const float* bkv      = (const float*)d_in[4];
    const float* rel_bias = (const float*)d_in[5];
    float* out = (float*)d_out;

    prep<<<PREP_BLOCKS, 256>>>(x, Wq, Wkv, rel_bias);

    cudaFuncSetAttribute(qkv_tc, cudaFuncAttributeMaxDynamicSharedMemorySize,
                         QKV_SMEM);
    qkv_tc<<<dim3(NTOTC / 128, MROWS / 128), 256, QKV_SMEM>>>(bq, bkv);

    cudaFuncSetAttribute(flash_tc, cudaFuncAttributeMaxDynamicSharedMemorySize,
                         FL_SMEM);
    flash_tc<<<dim3(8, BATCH * NHEAD), 256, FL_SMEM>>>(out);
}